// round 1
// baseline (speedup 1.0000x reference)
#include <cuda_runtime.h>
#include <cstdint>

// Problem constants
#define B_   64
#define T_   4096
#define NIN  64
#define U_   128
#define NOUT 64
#define CCH  64   // number of chunks
#define LCH  64   // chunk length  (CCH * LCH == T_)

// ---------------------------------------------------------------------------
// Scratch (static __device__ allocations — no runtime allocation)
// ---------------------------------------------------------------------------
__device__ float g_Ky[B_ * T_ * U_];      // 128 MB: Ky[b][t][u] = x[b,t,:] @ KT
__device__ float g_E[B_ * CCH * U_];      // chunk-local end states
__device__ float g_carry[B_ * CCH * U_];  // state entering each chunk
__device__ float g_M1[U_ * U_];
__device__ float g_M2[U_ * U_];           // final: AT^64

// ---------------------------------------------------------------------------
// Packed f32x2 helpers (Blackwell: 2x fp32 FMA throughput, PTX-only pattern)
// ---------------------------------------------------------------------------
__device__ __forceinline__ unsigned long long ffma2(unsigned long long a,
                                                    unsigned long long b,
                                                    unsigned long long c) {
    unsigned long long d;
    asm("fma.rn.f32x2 %0, %1, %2, %3;" : "=l"(d) : "l"(a), "l"(b), "l"(c));
    return d;
}
__device__ __forceinline__ unsigned long long dup2(float v) {
    unsigned long long r;
    asm("mov.b64 %0, {%1, %1};" : "=l"(r) : "f"(v));
    return r;
}
__device__ __forceinline__ unsigned long long pack2(float x, float y) {
    unsigned long long r;
    asm("mov.b64 %0, {%1, %2};" : "=l"(r) : "f"(x), "f"(y));
    return r;
}
__device__ __forceinline__ float2 unpack2(unsigned long long v) {
    float2 f;
    asm("mov.b64 {%0, %1}, %2;" : "=f"(f.x), "=f"(f.y) : "l"(v));
    return f;
}

// ---------------------------------------------------------------------------
// Kernel 1: Ky[b,t,:] = x[b,t,:] @ KT     ([B*T,64] @ [64,128])
// Block: 128 threads (thread = output column u), 256 rows/block in 32 tiles of 8.
// KT column lives in registers; x tile staged transposed in shared (broadcast reads).
// ---------------------------------------------------------------------------
__global__ __launch_bounds__(128) void ky_kernel(const float* __restrict__ x,
                                                 const float* __restrict__ KT) {
    const int u = threadIdx.x;
    float kt[NIN];
#pragma unroll
    for (int n = 0; n < NIN; n++) kt[n] = KT[n * U_ + u];

    __shared__ __align__(16) float xs[NIN * 8];  // [n][r], r = row-in-tile
    const int row0 = blockIdx.x * 256;

#pragma unroll 1
    for (int tile = 0; tile < 32; tile++) {
        const int r0 = row0 + tile * 8;
        // stage 8 rows x 64 cols of x, transposed
        float4 xv = reinterpret_cast<const float4*>(x + (size_t)r0 * NIN)[u];
        __syncthreads();   // previous tile's reads done
        {
            const int rr = u >> 4;          // row in tile: (u*4)/64
            const int n0 = (u & 15) * 4;    // input-feature base
            xs[(n0 + 0) * 8 + rr] = xv.x;
            xs[(n0 + 1) * 8 + rr] = xv.y;
            xs[(n0 + 2) * 8 + rr] = xv.z;
            xs[(n0 + 3) * 8 + rr] = xv.w;
        }
        __syncthreads();

        unsigned long long acc[4] = {0ull, 0ull, 0ull, 0ull};  // (0.f,0.f) packed
#pragma unroll
        for (int n = 0; n < NIN; n++) {
            unsigned long long kv = dup2(kt[n]);
            ulonglong2 a = *reinterpret_cast<const ulonglong2*>(&xs[n * 8]);
            ulonglong2 b = *reinterpret_cast<const ulonglong2*>(&xs[n * 8 + 4]);
            acc[0] = ffma2(a.x, kv, acc[0]);
            acc[1] = ffma2(a.y, kv, acc[1]);
            acc[2] = ffma2(b.x, kv, acc[2]);
            acc[3] = ffma2(b.y, kv, acc[3]);
        }
#pragma unroll
        for (int i = 0; i < 4; i++) {
            float2 f = unpack2(acc[i]);
            g_Ky[(size_t)(r0 + 2 * i)     * U_ + u] = f.x;
            g_Ky[(size_t)(r0 + 2 * i + 1) * U_ + u] = f.y;
        }
    }
}

// ---------------------------------------------------------------------------
// Kernel 2: O = A @ A   (128x128 matrix squaring, used 6x for AT^64)
// ---------------------------------------------------------------------------
__global__ __launch_bounds__(128) void matsq(const float* __restrict__ A,
                                             float* __restrict__ O) {
    const int r = blockIdx.x, u = threadIdx.x;
    __shared__ float row[U_];
    row[u] = A[r * U_ + u];
    __syncthreads();
    float acc = 0.f;
#pragma unroll 8
    for (int k = 0; k < U_; k++) acc = fmaf(row[k], A[k * U_ + u], acc);
    O[r * U_ + u] = acc;
}

// ---------------------------------------------------------------------------
// Kernels 3 & 5: chunk-local scan.
//   P3 = false : zero-init, store chunk-end state into g_E.
//   P3 = true  : init from g_carry, each step also emits y_t = s_{t+1} @ CyT.
// Block: 128 threads = 128 state columns, 8 batches per block (4 f32x2 accums).
// grid = (CCH, B_/8). AT column held in registers (128 regs/thread).
// ---------------------------------------------------------------------------
template <bool P3>
__global__ __launch_bounds__(128, 2) void scan_kernel(const float* __restrict__ AT,
                                                      const float* __restrict__ CyT,
                                                      float* __restrict__ yout) {
    const int c  = blockIdx.x;   // chunk
    const int bg = blockIdx.y;   // batch group
    const int u  = threadIdx.x;  // state column
    const int b0 = bg * 8;

    __shared__ __align__(16) float s_sh[2][U_ * 8];            // [k][batch], double buffered
    __shared__ __align__(16) float cy_sh[P3 ? U_ * NOUT : 8];  // CyT (pass 3 only)

    float at[U_];
#pragma unroll
    for (int k = 0; k < U_; k++) at[k] = AT[k * U_ + u];

    if (P3) {
#pragma unroll 1
        for (int i = u; i < U_ * NOUT; i += 128) cy_sh[i] = CyT[i];
#pragma unroll
        for (int j = 0; j < 8; j++)
            s_sh[0][u * 8 + j] = g_carry[((size_t)(b0 + j) * CCH + c) * U_ + u];
    } else {
#pragma unroll
        for (int j = 0; j < 8; j++) s_sh[0][u * 8 + j] = 0.f;
    }
    __syncthreads();

    const int o    = u & 63;   // output column (pass 3)
    const int bsel = u >> 6;   // which half of the 8 batches (pass 3)

    // prefetch Ky for first step
    float kyc[8];
#pragma unroll
    for (int j = 0; j < 8; j++)
        kyc[j] = g_Ky[((size_t)(b0 + j) * T_ + c * LCH) * U_ + u];

    int p = 0;
#pragma unroll 1
    for (int step = 0; step < LCH; step++) {
        const int t = c * LCH + step;

        float kyn[8];
        if (step + 1 < LCH) {
#pragma unroll
            for (int j = 0; j < 8; j++)
                kyn[j] = g_Ky[((size_t)(b0 + j) * T_ + t + 1) * U_ + u];
        } else {
#pragma unroll
            for (int j = 0; j < 8; j++) kyn[j] = 0.f;
        }

        unsigned long long acc[4];
#pragma unroll
        for (int i = 0; i < 4; i++) acc[i] = pack2(kyc[2 * i], kyc[2 * i + 1]);

#pragma unroll
        for (int k = 0; k < U_; k++) {
            unsigned long long av = dup2(at[k]);
            ulonglong2 sA = *reinterpret_cast<const ulonglong2*>(&s_sh[p][k * 8]);
            ulonglong2 sB = *reinterpret_cast<const ulonglong2*>(&s_sh[p][k * 8 + 4]);
            acc[0] = ffma2(sA.x, av, acc[0]);
            acc[1] = ffma2(sA.y, av, acc[1]);
            acc[2] = ffma2(sB.x, av, acc[2]);
            acc[3] = ffma2(sB.y, av, acc[3]);
        }

        const int q = p ^ 1;
        {
            float2 f0 = unpack2(acc[0]), f1 = unpack2(acc[1]);
            float2 f2 = unpack2(acc[2]), f3 = unpack2(acc[3]);
            float4* dst = reinterpret_cast<float4*>(&s_sh[q][u * 8]);
            dst[0] = make_float4(f0.x, f0.y, f1.x, f1.y);
            dst[1] = make_float4(f2.x, f2.y, f3.x, f3.y);
        }
        __syncthreads();  // new state visible to all; old buffer free for next step

        if (P3) {
            // y[b,t,o] = sum_k s_new[k] * CyT[k,o], 4 batches per thread
            unsigned long long yacc[2] = {0ull, 0ull};
#pragma unroll
            for (int k = 0; k < U_; k++) {
                unsigned long long cv = dup2(cy_sh[k * NOUT + o]);
                ulonglong2 sp =
                    *reinterpret_cast<const ulonglong2*>(&s_sh[q][k * 8 + bsel * 4]);
                yacc[0] = ffma2(sp.x, cv, yacc[0]);
                yacc[1] = ffma2(sp.y, cv, yacc[1]);
            }
            float2 y0 = unpack2(yacc[0]), y1 = unpack2(yacc[1]);
            const int bb = b0 + bsel * 4;
            yout[((size_t)(bb + 0) * T_ + t) * NOUT + o] = y0.x;
            yout[((size_t)(bb + 1) * T_ + t) * NOUT + o] = y0.y;
            yout[((size_t)(bb + 2) * T_ + t) * NOUT + o] = y1.x;
            yout[((size_t)(bb + 3) * T_ + t) * NOUT + o] = y1.y;
        }

        p = q;
#pragma unroll
        for (int j = 0; j < 8; j++) kyc[j] = kyn[j];
    }

    if (!P3) {
#pragma unroll
        for (int j = 0; j < 8; j++)
            g_E[((size_t)(b0 + j) * CCH + c) * U_ + u] = s_sh[p][u * 8 + j];
    }
}

// ---------------------------------------------------------------------------
// Kernel 4: carry scan across chunks.  carry[b,0]=0;
//           carry[b,c] = carry[b,c-1] @ AT^64 + E[b,c-1]
// One block per batch; M column (AT^64) in registers.
// ---------------------------------------------------------------------------
__global__ __launch_bounds__(128) void pass2_kernel() {
    const int b = blockIdx.x;
    const int u = threadIdx.x;
    __shared__ float ss[2][U_];
    float m[U_];
#pragma unroll
    for (int k = 0; k < U_; k++) m[k] = g_M2[k * U_ + u];

    float su = 0.f;
    ss[0][u] = 0.f;
    __syncthreads();

    int p = 0;
#pragma unroll 1
    for (int c = 0; c < CCH; c++) {
        g_carry[((size_t)b * CCH + c) * U_ + u] = su;
        float acc = g_E[((size_t)b * CCH + c) * U_ + u];
#pragma unroll
        for (int k = 0; k < U_; k++) acc = fmaf(ss[p][k], m[k], acc);
        su = acc;
        ss[p ^ 1][u] = acc;
        __syncthreads();
        p ^= 1;
    }
}

// ---------------------------------------------------------------------------
// Launch: inputs (metadata order) = x, AT, KT, CyT ; output f32 [64,4096,64]
// ---------------------------------------------------------------------------
extern "C" void kernel_launch(void* const* d_in, const int* in_sizes, int n_in,
                              void* d_out, int out_size) {
    const float* x   = (const float*)d_in[0];
    const float* AT  = (const float*)d_in[1];
    const float* KT  = (const float*)d_in[2];
    const float* CyT = (const float*)d_in[3];
    float* y = (float*)d_out;

    float *pM1, *pM2;
    cudaGetSymbolAddress((void**)&pM1, g_M1);
    cudaGetSymbolAddress((void**)&pM2, g_M2);

    // 1) Ky = x @ KT
    ky_kernel<<<(B_ * T_) / 256, 128>>>(x, KT);

    // 2) AT^64 by repeated squaring: AT^2,^4,^8,^16,^32,^64  -> g_M2
    matsq<<<128, 128>>>(AT,  pM1);
    matsq<<<128, 128>>>(pM1, pM2);
    matsq<<<128, 128>>>(pM2, pM1);
    matsq<<<128, 128>>>(pM1, pM2);
    matsq<<<128, 128>>>(pM2, pM1);
    matsq<<<128, 128>>>(pM1, pM2);

    // 3) chunk-local scans (zero init) -> E
    scan_kernel<false><<<dim3(CCH, B_ / 8), 128>>>(AT, CyT, y);

    // 4) carry scan across chunks -> carry
    pass2_kernel<<<B_, 128>>>();

    // 5) final scan with carries, fused output GEMV -> y
    scan_kernel<true><<<dim3(CCH, B_ / 8), 128>>>(AT, CyT, y);
}